// round 1
// baseline (speedup 1.0000x reference)
#include <cuda_runtime.h>
#include <cstdint>

// Problem dims
#define B_  32
#define S_  2048
#define E_  256
#define H_  256
#define M_  (B_ * S_)   // 65536
#define N_  (3 * H_)    // 768
#define K_  (2 * E_)    // 512

// Scratch: activated gates z|f|o, [M, 768] fp32  (~201 MB, static device array)
__device__ float g_gates[(size_t)M_ * N_];

__device__ __forceinline__ uint32_t f2tf(float x) {
    uint32_t r;
    asm("cvt.rna.tf32.f32 %0, %1;" : "=r"(r) : "f"(x));
    return r;
}

__device__ __forceinline__ float sigm(float x) {
    return 1.0f / (1.0f + __expf(-x));
}
__device__ __forceinline__ float tanh_fast(float x) {
    // 2*sigmoid(2x)-1 ; __expf is ~2ulp, plenty for 1e-3 tolerance
    return 2.0f / (1.0f + __expf(-2.0f * x)) - 1.0f;
}

// ---------------------------------------------------------------------------
// Kernel A: gates = [x_t, x_{t-1}] @ W + b, then activation, to g_gates.
// TF32 mma.sync, CTA tile 128x128, K-tile 32, 8 warps (2x4), warp tile 64x32.
// ---------------------------------------------------------------------------
__global__ __launch_bounds__(256, 1)
void gates_kernel(const float* __restrict__ x,
                  const float* __restrict__ W,
                  const float* __restrict__ bias)
{
    // pads chosen so pad % 32 == 4 -> conflict-free fragment loads
    __shared__ float sA[128 * 36];   // [row][k]  (BM=128, BK=32, pad 36)
    __shared__ float sB[32 * 132];   // [k][n]    (BK=32, BN=128, pad 132)

    const int tid  = threadIdx.x;
    const int lane = tid & 31;
    const int wid  = tid >> 5;
    const int warp_m = wid & 1;   // 2 warps along M
    const int warp_n = wid >> 1;  // 4 warps along N
    const int m0 = blockIdx.x * 128;
    const int n0 = blockIdx.y * 128;

    float acc[4][4][4];
#pragma unroll
    for (int a = 0; a < 4; a++)
#pragma unroll
        for (int b = 0; b < 4; b++)
#pragma unroll
            for (int c = 0; c < 4; c++) acc[a][b][c] = 0.0f;

    float4 regA[4], regB[4];

    auto load_tile = [&](int kt) {
        const int k0 = kt * 32;
#pragma unroll
        for (int i = 0; i < 4; i++) {
            int linear = tid + i * 256;       // 1024 float4 for A tile
            int row = linear >> 3;            // 128 rows, 8 float4 each
            int col = (linear & 7) << 2;
            int m = m0 + row;
            if (k0 < 256) {
                regA[i] = *(const float4*)(x + (long)m * E_ + k0 + col);
            } else {
                // prev-timestep half: x_flat[m*256 + k - 512], zero at t==0
                bool valid = (m & (S_ - 1)) != 0;
                if (valid)
                    regA[i] = *(const float4*)(x + (long)m * E_ + (k0 - 512) + col);
                else
                    regA[i] = make_float4(0.f, 0.f, 0.f, 0.f);
            }
        }
#pragma unroll
        for (int i = 0; i < 4; i++) {
            int linear = tid + i * 256;       // 1024 float4 for B tile
            int row = linear >> 5;            // 32 rows, 32 float4 each
            int col = (linear & 31) << 2;
            regB[i] = *(const float4*)(W + (long)(k0 + row) * N_ + n0 + col);
        }
    };

    auto store_smem = [&]() {
#pragma unroll
        for (int i = 0; i < 4; i++) {
            int linear = tid + i * 256;
            int row = linear >> 3;
            int col = (linear & 7) << 2;
            float4 v = regA[i];
            float4 cv;
            cv.x = __uint_as_float(f2tf(v.x));
            cv.y = __uint_as_float(f2tf(v.y));
            cv.z = __uint_as_float(f2tf(v.z));
            cv.w = __uint_as_float(f2tf(v.w));
            *(float4*)&sA[row * 36 + col] = cv;
        }
#pragma unroll
        for (int i = 0; i < 4; i++) {
            int linear = tid + i * 256;
            int row = linear >> 5;
            int col = (linear & 31) << 2;
            float4 v = regB[i];
            float4 cv;
            cv.x = __uint_as_float(f2tf(v.x));
            cv.y = __uint_as_float(f2tf(v.y));
            cv.z = __uint_as_float(f2tf(v.z));
            cv.w = __uint_as_float(f2tf(v.w));
            *(float4*)&sB[row * 132 + col] = cv;
        }
    };

    load_tile(0);
    store_smem();
    __syncthreads();

    for (int kt = 0; kt < 16; kt++) {
        if (kt < 15) load_tile(kt + 1);   // overlap global loads with MMA

#pragma unroll
        for (int ks = 0; ks < 4; ks++) {
            const int kk = ks * 8;
            uint32_t af[4][4];
            uint32_t bf[4][2];
#pragma unroll
            for (int mt = 0; mt < 4; mt++) {
                int r = warp_m * 64 + mt * 16 + (lane >> 2);
                int c = kk + (lane & 3);
                af[mt][0] = __float_as_uint(sA[r * 36 + c]);
                af[mt][1] = __float_as_uint(sA[(r + 8) * 36 + c]);
                af[mt][2] = __float_as_uint(sA[r * 36 + c + 4]);
                af[mt][3] = __float_as_uint(sA[(r + 8) * 36 + c + 4]);
            }
#pragma unroll
            for (int nt = 0; nt < 4; nt++) {
                int n = warp_n * 32 + nt * 8 + (lane >> 2);
                bf[nt][0] = __float_as_uint(sB[(kk + (lane & 3)) * 132 + n]);
                bf[nt][1] = __float_as_uint(sB[(kk + (lane & 3) + 4) * 132 + n]);
            }
#pragma unroll
            for (int mt = 0; mt < 4; mt++)
#pragma unroll
                for (int nt = 0; nt < 4; nt++) {
                    asm volatile(
                        "mma.sync.aligned.m16n8k8.row.col.f32.tf32.tf32.f32 "
                        "{%0,%1,%2,%3}, {%4,%5,%6,%7}, {%8,%9}, {%0,%1,%2,%3};"
                        : "+f"(acc[mt][nt][0]), "+f"(acc[mt][nt][1]),
                          "+f"(acc[mt][nt][2]), "+f"(acc[mt][nt][3])
                        : "r"(af[mt][0]), "r"(af[mt][1]),
                          "r"(af[mt][2]), "r"(af[mt][3]),
                          "r"(bf[nt][0]), "r"(bf[nt][1]));
                }
        }
        __syncthreads();
        if (kt < 15) {
            store_smem();
            __syncthreads();
        }
    }

    // Epilogue: bias + activation (col<256: tanh; else sigmoid), write g_gates
#pragma unroll
    for (int mt = 0; mt < 4; mt++) {
#pragma unroll
        for (int nt = 0; nt < 4; nt++) {
            int r    = m0 + warp_m * 64 + mt * 16 + (lane >> 2);
            int cgl  = n0 + warp_n * 32 + nt * 8 + ((lane & 3) << 1);
            bool isz = (cgl < 256);
            float b0 = bias[cgl];
            float b1 = bias[cgl + 1];

            float v0 = acc[mt][nt][0] + b0;
            float v1 = acc[mt][nt][1] + b1;
            float v2 = acc[mt][nt][2] + b0;
            float v3 = acc[mt][nt][3] + b1;
            if (isz) {
                v0 = tanh_fast(v0); v1 = tanh_fast(v1);
                v2 = tanh_fast(v2); v3 = tanh_fast(v3);
            } else {
                v0 = sigm(v0); v1 = sigm(v1);
                v2 = sigm(v2); v3 = sigm(v3);
            }
            *(float2*)&g_gates[(long)r * N_ + cgl]       = make_float2(v0, v1);
            *(float2*)&g_gates[(long)(r + 8) * N_ + cgl] = make_float2(v2, v3);
        }
    }
}

// ---------------------------------------------------------------------------
// Kernel B: fo-pool scan. One warp per (batch, 32 h-lanes): 256 CTAs x 32 thr.
// Unroll-8 so loads for 8 timesteps are batched (MLP) ahead of the serial
// dependence on c.
// ---------------------------------------------------------------------------
__global__ __launch_bounds__(32)
void scan_kernel(const int* __restrict__ mask, float* __restrict__ out)
{
    const int h = ((blockIdx.x & 7) << 5) + threadIdx.x;  // 8 chunks of 32 h
    const int b = blockIdx.x >> 3;

    const float* gp = g_gates + (long)b * S_ * N_ + h;

    int idx = mask[b] - 1;
    if (idx < 0) idx = 0;
    if (idx > S_ - 1) idx = S_ - 1;

    float* outT    = out;                             // hidden_temp [B,S,H]
    float* outHid  = out + (long)B_ * S_ * H_;        // hidden      [B,1,H]
    float* outCell = outHid + B_ * H_;                // cell_state  [B,1,H]

    float c = 0.0f;
    for (int t0 = 0; t0 < S_; t0 += 8) {
        float z[8], f[8], o[8];
#pragma unroll
        for (int j = 0; j < 8; j++) {
            const float* p = gp + (long)(t0 + j) * N_;
            z[j] = __ldg(p);
            f[j] = __ldg(p + 256);
            o[j] = __ldg(p + 512);
        }
#pragma unroll
        for (int j = 0; j < 8; j++) {
            // c = f*c + (1-f)*z  ==  z + f*(c - z)
            c = fmaf(f[j], c - z[j], z[j]);
            float hv = o[j] * c;
            outT[((long)b * S_ + t0 + j) * H_ + h] = hv;
            if (t0 + j == idx) {
                outHid[b * H_ + h]  = hv;
                outCell[b * H_ + h] = c;
            }
        }
    }
}

extern "C" void kernel_launch(void* const* d_in, const int* in_sizes, int n_in,
                              void* d_out, int out_size)
{
    const float* x    = (const float*)d_in[0];
    const int*   mask = (const int*)d_in[1];
    const float* W    = (const float*)d_in[2];
    const float* bias = (const float*)d_in[3];
    float* out = (float*)d_out;

    dim3 grid(M_ / 128, N_ / 128);   // 512 x 6
    gates_kernel<<<grid, 256>>>(x, W, bias);
    scan_kernel<<<B_ * (H_ / 32), 32>>>(mask, out);
}

// round 4
// speedup vs baseline: 2.3235x; 2.3235x over previous
#include <cuda_runtime.h>
#include <cuda_fp16.h>
#include <cstdint>

// Problem dims
#define B_  32
#define S_  2048
#define E_  256
#define H_  256
#define M_  (B_ * S_)   // 65536
#define N_  (3 * H_)    // 768
#define K_  (2 * E_)    // 512

#define CHUNKS 16
#define CHLEN  (S_ / CHUNKS)   // 128
#define CHAINS (B_ * H_)       // 8192

// Scratch (static device arrays; no allocation)
__device__ float  g_gates[(size_t)M_ * N_];   // activated z|f|o  [M,768]
__device__ __half g_x16[(size_t)M_ * E_];     // x in fp16
__device__ __half g_Wt16[(size_t)N_ * K_];    // W transposed fp16 [768,512]
__device__ float  g_Ac[CHUNKS * CHAINS];
__device__ float  g_Bc[CHUNKS * CHAINS];
__device__ float  g_c0[CHUNKS * CHAINS];

__device__ __forceinline__ float sigm(float x)      { return 1.0f / (1.0f + __expf(-x)); }
__device__ __forceinline__ float tanh_fast(float x) { return 2.0f / (1.0f + __expf(-2.0f * x)) - 1.0f; }

__device__ __forceinline__ uint32_t smem_u32(const void* p) {
    uint32_t a;
    asm("{ .reg .u64 t; cvta.to.shared.u64 t, %1; cvt.u32.u64 %0, t; }" : "=r"(a) : "l"(p));
    return a;
}

#define LDSM_X4(r0, r1, r2, r3, a)                                              \
    asm volatile("ldmatrix.sync.aligned.m8n8.x4.shared.b16 {%0,%1,%2,%3}, [%4];"\
                 : "=r"(r0), "=r"(r1), "=r"(r2), "=r"(r3) : "r"(a))

#define MMA_F16(c, a0, a1, a2, a3, b0, b1)                                      \
    asm volatile("mma.sync.aligned.m16n8k16.row.col.f32.f16.f16.f32 "           \
                 "{%0,%1,%2,%3}, {%4,%5,%6,%7}, {%8,%9}, {%0,%1,%2,%3};"        \
                 : "+f"((c)[0]), "+f"((c)[1]), "+f"((c)[2]), "+f"((c)[3])       \
                 : "r"(a0), "r"(a1), "r"(a2), "r"(a3), "r"(b0), "r"(b1))

__device__ __forceinline__ void cp16(uint32_t dst, const void* src, int sz) {
    asm volatile("cp.async.cg.shared.global [%0], [%1], 16, %2;" :: "r"(dst), "l"(src), "r"(sz));
}
#define CP_COMMIT() asm volatile("cp.async.commit_group;" ::: "memory")
#define CP_WAIT2()  asm volatile("cp.async.wait_group 2;" ::: "memory")

// ---------------------------------------------------------------------------
// x fp32 -> fp16
// ---------------------------------------------------------------------------
__global__ __launch_bounds__(256)
void convert_x(const float* __restrict__ x)
{
    long i = (long)blockIdx.x * 256 + threadIdx.x;     // one float4 pair each
    const float4* src = (const float4*)x;
    float4 v0 = src[2 * i], v1 = src[2 * i + 1];
    __half2 h0 = __floats2half2_rn(v0.x, v0.y);
    __half2 h1 = __floats2half2_rn(v0.z, v0.w);
    __half2 h2 = __floats2half2_rn(v1.x, v1.y);
    __half2 h3 = __floats2half2_rn(v1.z, v1.w);
    uint4 o;
    o.x = *(uint32_t*)&h0; o.y = *(uint32_t*)&h1;
    o.z = *(uint32_t*)&h2; o.w = *(uint32_t*)&h3;
    *((uint4*)g_x16 + i) = o;
}

// ---------------------------------------------------------------------------
// W [512,768] fp32 -> Wt16 [768,512] fp16 (transposed)
// ---------------------------------------------------------------------------
__global__ void prep_w(const float* __restrict__ W)
{
    __shared__ float t[32][33];
    int n = blockIdx.x * 32 + threadIdx.x;
    int k = blockIdx.y * 32 + threadIdx.y;
#pragma unroll
    for (int j = 0; j < 32; j += 8)
        t[threadIdx.y + j][threadIdx.x] = W[(long)(k + j) * N_ + n];
    __syncthreads();
    int n2 = blockIdx.x * 32 + threadIdx.y;
    int k2 = blockIdx.y * 32 + threadIdx.x;
#pragma unroll
    for (int j = 0; j < 32; j += 8)
        g_Wt16[(long)(n2 + j) * K_ + k2] = __float2half_rn(t[threadIdx.x][threadIdx.y + j]);
}

// ---------------------------------------------------------------------------
// GEMM: gates = [x_t, x_{t-1}] @ W + b, fp16 mma.sync m16n8k16, fp32 accum.
// CTA tile 128x128, BK=32, 8 warps (2x4), warp tile 64x32, 3-stage cp.async.
// smem row stride 40 halves (80B): banks (20*r mod 32) form a permutation ->
// conflict-free ldmatrix.
// B stored [n][k] k-contiguous -> NON-trans ldmatrix yields the col-major
// B fragment (lane L: n = L/4, k = 2*(L%4)+{0,1}).
// ---------------------------------------------------------------------------
#define RS        40                      // halves per smem row
#define A_BYTES   (128 * RS * 2)          // 10240
#define STAGE_SZ  (2 * A_BYTES)           // A + B
#define STAGES    3
#define SMEM_BYTES (STAGES * STAGE_SZ)    // 61440

__global__ __launch_bounds__(256, 2)
void gates_gemm(const float* __restrict__ bias)
{
    extern __shared__ char smem[];
    const uint32_t sb = smem_u32(smem);
    const int tid  = threadIdx.x;
    const int lane = tid & 31;
    const int wid  = tid >> 5;
    const int warp_m = wid & 1;
    const int warp_n = wid >> 1;
    const int m0 = blockIdx.y * 128;
    const int n0 = blockIdx.x * 128;

    auto stageA = [&](int s) -> uint32_t { return sb + s * STAGE_SZ; };
    auto stageB = [&](int s) -> uint32_t { return sb + s * STAGE_SZ + A_BYTES; };

    float acc[4][4][4];
#pragma unroll
    for (int a = 0; a < 4; a++)
#pragma unroll
        for (int b = 0; b < 4; b++)
#pragma unroll
            for (int c = 0; c < 4; c++) acc[a][b][c] = 0.0f;

    // per-thread load geometry: 512 chunks of 16B per (A|B) tile, 2 per thread
    auto load_tile = [&](int kt, int s) {
        const int k0 = kt * 32;
        const uint32_t ab = stageA(s), bb = stageB(s);
#pragma unroll
        for (int i = 0; i < 2; i++) {
            int idx = tid + i * 256;
            int r = idx >> 2, ci = idx & 3;          // row 0..127, 16B chunk 0..3
            uint32_t dst = ab + r * (RS * 2) + ci * 16;
            int m = m0 + r;
            const __half* src;
            int sz = 16;
            if (k0 < 256) {
                src = g_x16 + (long)m * E_ + k0 + ci * 8;
            } else if ((m & (S_ - 1)) == 0) {
                src = g_x16; sz = 0;                  // t==0: zero fill
            } else {
                src = g_x16 + (long)(m - 1) * E_ + (k0 - 256) + ci * 8;
            }
            cp16(dst, src, sz);
        }
#pragma unroll
        for (int i = 0; i < 2; i++) {
            int idx = tid + i * 256;
            int r = idx >> 2, ci = idx & 3;
            uint32_t dst = bb + r * (RS * 2) + ci * 16;
            cp16(dst, g_Wt16 + (long)(n0 + r) * K_ + k0 + ci * 8, 16);
        }
    };

    load_tile(0, 0); CP_COMMIT();
    load_tile(1, 1); CP_COMMIT();
    load_tile(2, 2); CP_COMMIT();

    for (int kt = 0; kt < 16; kt++) {
        const int s = kt % STAGES;
        CP_WAIT2();
        __syncthreads();

        const uint32_t ab = stageA(s), bb = stageB(s);
#pragma unroll
        for (int ks = 0; ks < 2; ks++) {
            const int kk = ks * 16;
            uint32_t af[4][4], bf[4][2];
            // A fragments: 4 m-tiles, ldmatrix.x4 each (non-trans, [m][k])
#pragma unroll
            for (int mt = 0; mt < 4; mt++) {
                int mBase = warp_m * 64 + mt * 16;
                int mi = lane >> 3;                       // matrix index 0..3
                int row = mBase + ((mi & 1) << 3) + (lane & 7);
                int col = kk + ((mi >> 1) << 3);
                uint32_t a = ab + (row * RS + col) * 2;
                LDSM_X4(af[mt][0], af[mt][1], af[mt][2], af[mt][3], a);
            }
            // B fragments: 2 n-tile pairs, ldmatrix.x4 each (non-trans, [n][k])
            // matrix order: (n0-7,k0-7)->b0 t0, (n0-7,k8-15)->b1 t0,
            //               (n8-15,k0-7)->b0 t1, (n8-15,k8-15)->b1 t1
#pragma unroll
            for (int p = 0; p < 2; p++) {
                int nBase = warp_n * 32 + p * 16;
                int mi = lane >> 3;
                int row = nBase + ((mi >> 1) << 3) + (lane & 7);
                int col = kk + ((mi & 1) << 3);
                uint32_t a = bb + (row * RS + col) * 2;
                LDSM_X4(bf[2 * p][0], bf[2 * p][1], bf[2 * p + 1][0], bf[2 * p + 1][1], a);
            }
#pragma unroll
            for (int mt = 0; mt < 4; mt++)
#pragma unroll
                for (int nt = 0; nt < 4; nt++)
                    MMA_F16(acc[mt][nt], af[mt][0], af[mt][1], af[mt][2], af[mt][3],
                            bf[nt][0], bf[nt][1]);
        }
        __syncthreads();
        if (kt + STAGES < 16) load_tile(kt + STAGES, s);
        CP_COMMIT();    // always commit (possibly empty) to keep wait_group math
    }

    // Epilogue: bias + activation, write g_gates fp32
#pragma unroll
    for (int mt = 0; mt < 4; mt++) {
#pragma unroll
        for (int nt = 0; nt < 4; nt++) {
            int r   = m0 + warp_m * 64 + mt * 16 + (lane >> 2);
            int cgl = n0 + warp_n * 32 + nt * 8 + ((lane & 3) << 1);
            bool isz = (cgl < 256);
            float b0 = __ldg(bias + cgl);
            float b1 = __ldg(bias + cgl + 1);
            float v0 = acc[mt][nt][0] + b0;
            float v1 = acc[mt][nt][1] + b1;
            float v2 = acc[mt][nt][2] + b0;
            float v3 = acc[mt][nt][3] + b1;
            if (isz) {
                v0 = tanh_fast(v0); v1 = tanh_fast(v1);
                v2 = tanh_fast(v2); v3 = tanh_fast(v3);
            } else {
                v0 = sigm(v0); v1 = sigm(v1);
                v2 = sigm(v2); v3 = sigm(v3);
            }
            *(float2*)&g_gates[(long)r * N_ + cgl]       = make_float2(v0, v1);
            *(float2*)&g_gates[(long)(r + 8) * N_ + cgl] = make_float2(v2, v3);
        }
    }
}

// ---------------------------------------------------------------------------
// Scan pass 1: per (chain, chunk): A = prod(f), B = c(chunk | c_in = 0)
// ---------------------------------------------------------------------------
__global__ __launch_bounds__(256)
void scan_p1()
{
    const int b = blockIdx.x >> 4, q = blockIdx.x & 15, h = threadIdx.x;
    const float* gp = g_gates + (long)(b * S_ + q * CHLEN) * N_ + h;

    float a = 1.0f, c = 0.0f;
    for (int t0 = 0; t0 < CHLEN; t0 += 8) {
        float z[8], f[8];
#pragma unroll
        for (int j = 0; j < 8; j++) {
            const float* p = gp + (long)(t0 + j) * N_;
            z[j] = __ldg(p);
            f[j] = __ldg(p + 256);
        }
#pragma unroll
        for (int j = 0; j < 8; j++) {
            c = fmaf(f[j], c - z[j], z[j]);
            a *= f[j];
        }
    }
    const int chain = b * H_ + h;
    g_Ac[q * CHAINS + chain] = a;
    g_Bc[q * CHAINS + chain] = c;
}

// ---------------------------------------------------------------------------
// Scan pass 2: sequential combine over 16 chunks -> chunk-initial c
// ---------------------------------------------------------------------------
__global__ __launch_bounds__(256)
void scan_p2()
{
    const int chain = blockIdx.x * 256 + threadIdx.x;
    float c = 0.0f;
#pragma unroll
    for (int q = 0; q < CHUNKS; q++) {
        g_c0[q * CHAINS + chain] = c;
        c = g_Ac[q * CHAINS + chain] * c + g_Bc[q * CHAINS + chain];
    }
}

// ---------------------------------------------------------------------------
// Scan pass 3: within-chunk scan with correct initial c; write outputs
// ---------------------------------------------------------------------------
__global__ __launch_bounds__(256)
void scan_p3(const int* __restrict__ mask, float* __restrict__ out)
{
    const int b = blockIdx.x >> 4, q = blockIdx.x & 15, h = threadIdx.x;
    const int chain = b * H_ + h;
    const float* gp = g_gates + (long)(b * S_ + q * CHLEN) * N_ + h;

    int idx = mask[b] - 1;
    if (idx < 0) idx = 0;
    if (idx > S_ - 1) idx = S_ - 1;

    float* outT    = out + (long)(b * S_ + q * CHLEN) * H_ + h;
    float* outHid  = out + (long)B_ * S_ * H_;
    float* outCell = outHid + B_ * H_;

    float c = g_c0[q * CHAINS + chain];
    for (int t0 = 0; t0 < CHLEN; t0 += 8) {
        float z[8], f[8], o[8];
#pragma unroll
        for (int j = 0; j < 8; j++) {
            const float* p = gp + (long)(t0 + j) * N_;
            z[j] = __ldg(p);
            f[j] = __ldg(p + 256);
            o[j] = __ldg(p + 512);
        }
#pragma unroll
        for (int j = 0; j < 8; j++) {
            c = fmaf(f[j], c - z[j], z[j]);
            float hv = o[j] * c;
            outT[(long)(t0 + j) * H_] = hv;
            if (q * CHLEN + t0 + j == idx) {
                outHid[chain]  = hv;
                outCell[chain] = c;
            }
        }
    }
}

extern "C" void kernel_launch(void* const* d_in, const int* in_sizes, int n_in,
                              void* d_out, int out_size)
{
    const float* x    = (const float*)d_in[0];
    const int*   mask = (const int*)d_in[1];
    const float* W    = (const float*)d_in[2];
    const float* bias = (const float*)d_in[3];
    float* out = (float*)d_out;

    cudaFuncSetAttribute(gates_gemm, cudaFuncAttributeMaxDynamicSharedMemorySize, SMEM_BYTES);

    convert_x<<<M_ * E_ / 8 / 256, 256>>>(x);
    prep_w<<<dim3(24, 16), dim3(32, 8)>>>(W);
    gates_gemm<<<dim3(6, 512), 256, SMEM_BYTES>>>(bias);
    scan_p1<<<512, 256>>>();
    scan_p2<<<32, 256>>>();
    scan_p3<<<512, 256>>>(mask, out);
}

// round 5
// speedup vs baseline: 2.4296x; 1.0457x over previous
#include <cuda_runtime.h>
#include <cuda_fp16.h>
#include <cstdint>

// Problem dims
#define B_  32
#define S_  2048
#define E_  256
#define H_  256
#define M_  (B_ * S_)   // 65536
#define N_  (3 * H_)    // 768
#define K_  (2 * E_)    // 512

#define CHUNKS 16
#define CHLEN  (S_ / CHUNKS)   // 128
#define CHAINS (B_ * H_)       // 8192

// Scratch (static device arrays; no allocation)
__device__ __half g_gates[(size_t)M_ * N_];   // activated z|f|o  [M,768] fp16
__device__ __half g_x16[(size_t)M_ * E_];     // x in fp16
__device__ __half g_Wt16[(size_t)N_ * K_];    // W transposed fp16 [768,512]
__device__ float  g_Ac[CHUNKS * CHAINS];
__device__ float  g_Bc[CHUNKS * CHAINS];
__device__ float  g_c0[CHUNKS * CHAINS];

__device__ __forceinline__ float sigm(float x)      { return 1.0f / (1.0f + __expf(-x)); }
__device__ __forceinline__ float tanh_fast(float x) { return 2.0f / (1.0f + __expf(-2.0f * x)) - 1.0f; }

__device__ __forceinline__ uint32_t smem_u32(const void* p) {
    uint32_t a;
    asm("{ .reg .u64 t; cvta.to.shared.u64 t, %1; cvt.u32.u64 %0, t; }" : "=r"(a) : "l"(p));
    return a;
}

#define LDSM_X4(r0, r1, r2, r3, a)                                              \
    asm volatile("ldmatrix.sync.aligned.m8n8.x4.shared.b16 {%0,%1,%2,%3}, [%4];"\
                 : "=r"(r0), "=r"(r1), "=r"(r2), "=r"(r3) : "r"(a))

#define MMA_F16(c, a0, a1, a2, a3, b0, b1)                                      \
    asm volatile("mma.sync.aligned.m16n8k16.row.col.f32.f16.f16.f32 "           \
                 "{%0,%1,%2,%3}, {%4,%5,%6,%7}, {%8,%9}, {%0,%1,%2,%3};"        \
                 : "+f"((c)[0]), "+f"((c)[1]), "+f"((c)[2]), "+f"((c)[3])       \
                 : "r"(a0), "r"(a1), "r"(a2), "r"(a3), "r"(b0), "r"(b1))

__device__ __forceinline__ void cp16(uint32_t dst, const void* src, int sz) {
    asm volatile("cp.async.cg.shared.global [%0], [%1], 16, %2;" :: "r"(dst), "l"(src), "r"(sz));
}
#define CP_COMMIT() asm volatile("cp.async.commit_group;" ::: "memory")
#define CP_WAIT3()  asm volatile("cp.async.wait_group 3;" ::: "memory")

// ---------------------------------------------------------------------------
// x fp32 -> fp16
// ---------------------------------------------------------------------------
__global__ __launch_bounds__(256)
void convert_x(const float* __restrict__ x)
{
    long i = (long)blockIdx.x * 256 + threadIdx.x;     // one float4 pair each
    const float4* src = (const float4*)x;
    float4 v0 = src[2 * i], v1 = src[2 * i + 1];
    __half2 h0 = __floats2half2_rn(v0.x, v0.y);
    __half2 h1 = __floats2half2_rn(v0.z, v0.w);
    __half2 h2 = __floats2half2_rn(v1.x, v1.y);
    __half2 h3 = __floats2half2_rn(v1.z, v1.w);
    uint4 o;
    o.x = *(uint32_t*)&h0; o.y = *(uint32_t*)&h1;
    o.z = *(uint32_t*)&h2; o.w = *(uint32_t*)&h3;
    *((uint4*)g_x16 + i) = o;
}

// ---------------------------------------------------------------------------
// W [512,768] fp32 -> Wt16 [768,512] fp16 (transposed)
// ---------------------------------------------------------------------------
__global__ void prep_w(const float* __restrict__ W)
{
    __shared__ float t[32][33];
    int n = blockIdx.x * 32 + threadIdx.x;
    int k = blockIdx.y * 32 + threadIdx.y;
#pragma unroll
    for (int j = 0; j < 32; j += 8)
        t[threadIdx.y + j][threadIdx.x] = W[(long)(k + j) * N_ + n];
    __syncthreads();
    int n2 = blockIdx.x * 32 + threadIdx.y;
    int k2 = blockIdx.y * 32 + threadIdx.x;
#pragma unroll
    for (int j = 0; j < 32; j += 8)
        g_Wt16[(long)(n2 + j) * K_ + k2] = __float2half_rn(t[threadIdx.x][threadIdx.y + j]);
}

// ---------------------------------------------------------------------------
// GEMM: gates = [x_t, x_{t-1}] @ W + b, fp16 mma.sync m16n8k16, fp32 accum.
// CTA tile 128x128, BK=32, 8 warps (2x4), warp tile 64x32, 4-stage cp.async.
// smem row stride 40 halves (80B): conflict-free ldmatrix.
// B stored [n][k] k-contiguous -> NON-trans ldmatrix = col-major B fragment.
// ---------------------------------------------------------------------------
#define RS        40                      // halves per smem row
#define A_BYTES   (128 * RS * 2)          // 10240
#define STAGE_SZ  (2 * A_BYTES)           // A + B = 20480
#define STAGES    4
#define SMEM_BYTES (STAGES * STAGE_SZ)    // 81920

__global__ __launch_bounds__(256, 2)
void gates_gemm(const float* __restrict__ bias)
{
    extern __shared__ char smem[];
    const uint32_t sb = smem_u32(smem);
    const int tid  = threadIdx.x;
    const int lane = tid & 31;
    const int wid  = tid >> 5;
    const int warp_m = wid & 1;
    const int warp_n = wid >> 1;
    const int m0 = blockIdx.y * 128;
    const int n0 = blockIdx.x * 128;

    auto stageA = [&](int s) -> uint32_t { return sb + s * STAGE_SZ; };
    auto stageB = [&](int s) -> uint32_t { return sb + s * STAGE_SZ + A_BYTES; };

    float acc[4][4][4];
#pragma unroll
    for (int a = 0; a < 4; a++)
#pragma unroll
        for (int b = 0; b < 4; b++)
#pragma unroll
            for (int c = 0; c < 4; c++) acc[a][b][c] = 0.0f;

    auto load_tile = [&](int kt, int s) {
        const int k0 = kt * 32;
        const uint32_t ab = stageA(s), bb = stageB(s);
#pragma unroll
        for (int i = 0; i < 2; i++) {
            int idx = tid + i * 256;
            int r = idx >> 2, ci = idx & 3;          // row 0..127, 16B chunk 0..3
            uint32_t dst = ab + r * (RS * 2) + ci * 16;
            int m = m0 + r;
            const __half* src;
            int sz = 16;
            if (k0 < 256) {
                src = g_x16 + (long)m * E_ + k0 + ci * 8;
            } else if ((m & (S_ - 1)) == 0) {
                src = g_x16; sz = 0;                  // t==0: zero fill
            } else {
                src = g_x16 + (long)(m - 1) * E_ + (k0 - 256) + ci * 8;
            }
            cp16(dst, src, sz);
        }
#pragma unroll
        for (int i = 0; i < 2; i++) {
            int idx = tid + i * 256;
            int r = idx >> 2, ci = idx & 3;
            uint32_t dst = bb + r * (RS * 2) + ci * 16;
            cp16(dst, g_Wt16 + (long)(n0 + r) * K_ + k0 + ci * 8, 16);
        }
    };

    load_tile(0, 0); CP_COMMIT();
    load_tile(1, 1); CP_COMMIT();
    load_tile(2, 2); CP_COMMIT();
    load_tile(3, 3); CP_COMMIT();

    for (int kt = 0; kt < 16; kt++) {
        const int s = kt % STAGES;
        CP_WAIT3();
        __syncthreads();

        const uint32_t ab = stageA(s), bb = stageB(s);
#pragma unroll
        for (int ks = 0; ks < 2; ks++) {
            const int kk = ks * 16;
            uint32_t af[4][4], bf[4][2];
#pragma unroll
            for (int mt = 0; mt < 4; mt++) {
                int mBase = warp_m * 64 + mt * 16;
                int mi = lane >> 3;
                int row = mBase + ((mi & 1) << 3) + (lane & 7);
                int col = kk + ((mi >> 1) << 3);
                uint32_t a = ab + (row * RS + col) * 2;
                LDSM_X4(af[mt][0], af[mt][1], af[mt][2], af[mt][3], a);
            }
#pragma unroll
            for (int p = 0; p < 2; p++) {
                int nBase = warp_n * 32 + p * 16;
                int mi = lane >> 3;
                int row = nBase + ((mi >> 1) << 3) + (lane & 7);
                int col = kk + ((mi & 1) << 3);
                uint32_t a = bb + (row * RS + col) * 2;
                LDSM_X4(bf[2 * p][0], bf[2 * p][1], bf[2 * p + 1][0], bf[2 * p + 1][1], a);
            }
#pragma unroll
            for (int mt = 0; mt < 4; mt++)
#pragma unroll
                for (int nt = 0; nt < 4; nt++)
                    MMA_F16(acc[mt][nt], af[mt][0], af[mt][1], af[mt][2], af[mt][3],
                            bf[nt][0], bf[nt][1]);
        }
        __syncthreads();
        if (kt + STAGES < 16) load_tile(kt + STAGES, s);
        CP_COMMIT();    // always commit (possibly empty) to keep wait_group math
    }

    // Epilogue: bias + activation, write g_gates fp16
#pragma unroll
    for (int mt = 0; mt < 4; mt++) {
#pragma unroll
        for (int nt = 0; nt < 4; nt++) {
            int r   = m0 + warp_m * 64 + mt * 16 + (lane >> 2);
            int cgl = n0 + warp_n * 32 + nt * 8 + ((lane & 3) << 1);
            bool isz = (cgl < 256);
            float b0 = __ldg(bias + cgl);
            float b1 = __ldg(bias + cgl + 1);
            float v0 = acc[mt][nt][0] + b0;
            float v1 = acc[mt][nt][1] + b1;
            float v2 = acc[mt][nt][2] + b0;
            float v3 = acc[mt][nt][3] + b1;
            if (isz) {
                v0 = tanh_fast(v0); v1 = tanh_fast(v1);
                v2 = tanh_fast(v2); v3 = tanh_fast(v3);
            } else {
                v0 = sigm(v0); v1 = sigm(v1);
                v2 = sigm(v2); v3 = sigm(v3);
            }
            *(__half2*)&g_gates[(long)r * N_ + cgl]       = __floats2half2_rn(v0, v1);
            *(__half2*)&g_gates[(long)(r + 8) * N_ + cgl] = __floats2half2_rn(v2, v3);
        }
    }
}

// ---------------------------------------------------------------------------
// Scan pass 1: per (chain, chunk): A = prod(f), B = c(chunk | c_in = 0)
// ---------------------------------------------------------------------------
__global__ __launch_bounds__(256)
void scan_p1()
{
    const int b = blockIdx.x >> 4, q = blockIdx.x & 15, h = threadIdx.x;
    const __half* gp = g_gates + (long)(b * S_ + q * CHLEN) * N_ + h;

    float a = 1.0f, c = 0.0f;
    for (int t0 = 0; t0 < CHLEN; t0 += 8) {
        float z[8], f[8];
#pragma unroll
        for (int j = 0; j < 8; j++) {
            const __half* p = gp + (long)(t0 + j) * N_;
            z[j] = __half2float(__ldg(p));
            f[j] = __half2float(__ldg(p + 256));
        }
#pragma unroll
        for (int j = 0; j < 8; j++) {
            c = fmaf(f[j], c - z[j], z[j]);
            a *= f[j];
        }
    }
    const int chain = b * H_ + h;
    g_Ac[q * CHAINS + chain] = a;
    g_Bc[q * CHAINS + chain] = c;
}

// ---------------------------------------------------------------------------
// Scan pass 2: sequential combine over 16 chunks -> chunk-initial c
// ---------------------------------------------------------------------------
__global__ __launch_bounds__(256)
void scan_p2()
{
    const int chain = blockIdx.x * 256 + threadIdx.x;
    float c = 0.0f;
#pragma unroll
    for (int q = 0; q < CHUNKS; q++) {
        g_c0[q * CHAINS + chain] = c;
        c = g_Ac[q * CHAINS + chain] * c + g_Bc[q * CHAINS + chain];
    }
}

// ---------------------------------------------------------------------------
// Scan pass 3: within-chunk scan with correct initial c; write outputs
// ---------------------------------------------------------------------------
__global__ __launch_bounds__(256)
void scan_p3(const int* __restrict__ mask, float* __restrict__ out)
{
    const int b = blockIdx.x >> 4, q = blockIdx.x & 15, h = threadIdx.x;
    const int chain = b * H_ + h;
    const __half* gp = g_gates + (long)(b * S_ + q * CHLEN) * N_ + h;

    int idx = mask[b] - 1;
    if (idx < 0) idx = 0;
    if (idx > S_ - 1) idx = S_ - 1;

    float* outT    = out + (long)(b * S_ + q * CHLEN) * H_ + h;
    float* outHid  = out + (long)B_ * S_ * H_;
    float* outCell = outHid + B_ * H_;

    float c = g_c0[q * CHAINS + chain];
    for (int t0 = 0; t0 < CHLEN; t0 += 8) {
        float z[8], f[8], o[8];
#pragma unroll
        for (int j = 0; j < 8; j++) {
            const __half* p = gp + (long)(t0 + j) * N_;
            z[j] = __half2float(__ldg(p));
            f[j] = __half2float(__ldg(p + 256));
            o[j] = __half2float(__ldg(p + 512));
        }
#pragma unroll
        for (int j = 0; j < 8; j++) {
            c = fmaf(f[j], c - z[j], z[j]);
            float hv = o[j] * c;
            outT[(long)(t0 + j) * H_] = hv;
            if (q * CHLEN + t0 + j == idx) {
                outHid[chain]  = hv;
                outCell[chain] = c;
            }
        }
    }
}

extern "C" void kernel_launch(void* const* d_in, const int* in_sizes, int n_in,
                              void* d_out, int out_size)
{
    const float* x    = (const float*)d_in[0];
    const int*   mask = (const int*)d_in[1];
    const float* W    = (const float*)d_in[2];
    const float* bias = (const float*)d_in[3];
    float* out = (float*)d_out;

    cudaFuncSetAttribute(gates_gemm, cudaFuncAttributeMaxDynamicSharedMemorySize, SMEM_BYTES);

    convert_x<<<M_ * E_ / 8 / 256, 256>>>(x);
    prep_w<<<dim3(24, 16), dim3(32, 8)>>>(W);
    gates_gemm<<<dim3(6, 512), 256, SMEM_BYTES>>>(bias);
    scan_p1<<<512, 256>>>();
    scan_p2<<<32, 256>>>();
    scan_p3<<<512, 256>>>(mask, out);
}